// round 16
// baseline (speedup 1.0000x reference)
#include <cuda_runtime.h>

#define BB 8
#define TT 2048
#define EE 1024
#define HH 128
#define MM (BB*TT)
#define SCALE 0.08838834764831845f   // 1/sqrt(128)

// Q/K/V in FRAGMENT-TILE layout: per 64-row block, 64 tiles x 128 floats.
__device__ float g_Q[MM*HH];
__device__ float g_K[MM*HH];
__device__ float g_V[MM*HH];
// W in B-fragment-tile layout (tf32-rounded): per 32-k block, 32 tiles x 128.
__device__ float g_Wf[3][EE*HH];

__device__ __forceinline__ float f2tf(float f) {
    unsigned r;
    asm("cvt.rna.tf32.f32 %0, %1;" : "=r"(r) : "f"(f));
    return __uint_as_float(r);
}

__device__ __forceinline__ void mma_tf32(float* c,
    unsigned a0, unsigned a1, unsigned a2, unsigned a3,
    unsigned b0, unsigned b1)
{
    asm volatile(
        "mma.sync.aligned.m16n8k8.row.col.f32.tf32.tf32.f32 "
        "{%0,%1,%2,%3},{%4,%5,%6,%7},{%8,%9},{%0,%1,%2,%3};"
        : "+f"(c[0]), "+f"(c[1]), "+f"(c[2]), "+f"(c[3])
        : "r"(a0), "r"(a1), "r"(a2), "r"(a3), "r"(b0), "r"(b1));
}
#define U(x) __float_as_uint(x)

__device__ __forceinline__ void cp_async16(unsigned saddr, const void* gaddr) {
    asm volatile("cp.async.cg.shared.global [%0], [%1], 16;"
                 :: "r"(saddr), "l"(gaddr));
}
#define CP_COMMIT() asm volatile("cp.async.commit_group;")
#define CP_WAIT0()  asm volatile("cp.async.wait_group 0;")

// Scatter index into Q/K/V fragment-tile layout (per 64-row block of 8192).
__device__ __forceinline__ size_t frag_idx(int w3, int m, int c) {
    int blk = m >> 6, R = m & 63;
    int tile, lane, reg;
    if (w3 == 0) {
        tile = (R >> 4) * 16 + (c >> 3);
        lane = ((R & 7) << 2) | (c & 3);
        reg  = ((R >> 3) & 1) | (((c >> 2) & 1) << 1);
    } else if (w3 == 1) {
        tile = (R >> 3) * 8 + (c >> 4);
        lane = ((R & 7) << 2) | (c & 3);
        reg  = (c >> 2) & 3;
    } else {
        tile = (c >> 3) * 4 + (R >> 4);
        lane = ((c & 7) << 2) | (R & 3);
        reg  = (R >> 2) & 3;
    }
    return (size_t)blk * 8192 + tile * 128 + lane * 4 + reg;
}

// ---------------------------------------------------------------------------
// Kernel 0: permute W[E,H] -> B-frag tiles (per 32-k block: 32 tiles x 128).
// tile = (n>>3)*2 + (kk>>4); lane = ((n&7)<<2)|(kk&3); reg = (kk>>2)&3 (kk&15)
// ---------------------------------------------------------------------------
__global__ __launch_bounds__(256) void wperm_kernel(
    const float* __restrict__ Wq,
    const float* __restrict__ Wk,
    const float* __restrict__ Wv)
{
    const int blk = blockIdx.x;           // 32-k block, 0..31
    const int w3  = blockIdx.y;
    const float* Wp = (w3 == 0) ? Wq : ((w3 == 1) ? Wk : Wv);
    float* outp = g_Wf[w3] + blk * 4096;

    for (int e = 0; e < 16; e++) {
        int idx = threadIdx.x + e * 256;  // 0..4095
        int kk = idx >> 7;                // local k, 0..31
        int n  = idx & 127;
        float v = Wp[(size_t)(blk * 32 + kk) * HH + n];
        int kc = kk & 15;
        int tile = (n >> 3) * 2 + (kk >> 4);
        int lane = ((n & 7) << 2) | (kc & 3);
        int reg  = kc >> 2;
        outp[tile * 128 + lane * 4 + reg] = f2tf(v);
    }
}

// ---------------------------------------------------------------------------
// Kernel 1: QKV projection. cp.async 2-stage W (pre-permuted frag tiles),
// double-buffered As, ONE barrier per 32-k iteration. Fragment scatter epi.
// smem: As 2x128x36 + Wf 2x4096 = 69632 B -> 2 CTAs/SM.
// ---------------------------------------------------------------------------
#define QKV_SMEM ((2*128*36 + 2*4096) * 4)

__global__ __launch_bounds__(256, 2) void qkv_kernel(
    const float* __restrict__ x,
    const float* __restrict__ Wq,
    const float* __restrict__ Wk,
    const float* __restrict__ Wv)
{
    extern __shared__ float sh2[];
    float* Asb = sh2;                 // 2 stages x [128][36]
    float* Wfs = sh2 + 2 * 128 * 36;  // 2 stages x 4096

    const int mb = blockIdx.x;
    const int w3 = blockIdx.y;
    float* outp = (w3 == 0) ? g_Q : ((w3 == 1) ? g_K : g_V);
    const float oscale = (w3 == 0) ? SCALE : 1.0f;
    const float* Wfg = g_Wf[w3];

    const int tid  = threadIdx.x;
    const int lane = tid & 31;
    const int w    = tid >> 5;
    const int g    = lane >> 2;
    const int t4   = lane & 3;
    const int wm   = (w >> 1) * 32;
    const int ntb  = (w & 1) * 8;     // base n-tile for this warp
    const int m0   = mb * 128;

    float acc[2][8][4];
#pragma unroll
    for (int mt = 0; mt < 2; mt++)
#pragma unroll
        for (int nt = 0; nt < 8; nt++)
#pragma unroll
            for (int i = 0; i < 4; i++) acc[mt][nt][i] = 0.f;

    // ---- prologue ----
    float4 xa[4];
#pragma unroll
    for (int i = 0; i < 4; i++) {           // prefetch x block 0
        int lin = tid + i * 256;
        int r = lin >> 3, c = (lin & 7) * 4;
        xa[i] = *(const float4*)&x[(size_t)(m0 + r) * EE + c];
    }
#pragma unroll
    for (int i = 0; i < 4; i++) {           // fill As stage 0
        int lin = tid + i * 256;
        int r = lin >> 3, c = (lin & 7) * 4;
        float* As0 = Asb + r * 36 + c;
        As0[0] = f2tf(xa[i].x); As0[1] = f2tf(xa[i].y);
        As0[2] = f2tf(xa[i].z); As0[3] = f2tf(xa[i].w);
    }
#pragma unroll
    for (int i = 0; i < 4; i++) {           // prefetch x block 1
        int lin = tid + i * 256;
        int r = lin >> 3, c = (lin & 7) * 4;
        xa[i] = *(const float4*)&x[(size_t)(m0 + r) * EE + 32 + c];
    }
    {                                        // cp.async W block 0 -> stage 0
        unsigned wb = (unsigned)__cvta_generic_to_shared(Wfs);
#pragma unroll
        for (int i = 0; i < 4; i++) {
            int lin = tid + i * 256;
            cp_async16(wb + lin * 16, (const char*)Wfg + lin * 16);
        }
        CP_COMMIT();
    }

    for (int it = 0; it < 32; it++) {
        const int st = it & 1;
        CP_WAIT0();
        __syncthreads();      // W[it] + As[it] visible; prev compute done

        if (it + 1 < 32) {
            // cp.async W block it+1 into other stage
            unsigned wb = (unsigned)__cvta_generic_to_shared(Wfs + (st ^ 1) * 4096);
            const char* wg = (const char*)(Wfg + (size_t)(it + 1) * 4096);
#pragma unroll
            for (int i = 0; i < 4; i++) {
                int lin = tid + i * 256;
                cp_async16(wb + lin * 16, wg + lin * 16);
            }
            CP_COMMIT();
            // fill As other stage from xa (block it+1)
            float* Asn = Asb + (st ^ 1) * 128 * 36;
#pragma unroll
            for (int i = 0; i < 4; i++) {
                int lin = tid + i * 256;
                int r = lin >> 3, c = (lin & 7) * 4;
                float* p = Asn + r * 36 + c;
                p[0] = f2tf(xa[i].x); p[1] = f2tf(xa[i].y);
                p[2] = f2tf(xa[i].z); p[3] = f2tf(xa[i].w);
            }
            // prefetch x block it+2
            if (it + 2 < 32) {
                int kn = (it + 2) * 32;
#pragma unroll
                for (int i = 0; i < 4; i++) {
                    int lin = tid + i * 256;
                    int r = lin >> 3, c = (lin & 7) * 4;
                    xa[i] = *(const float4*)&x[(size_t)(m0 + r) * EE + kn + c];
                }
            }
        }

        // ---- compute: 4 k-steps as 2 ksp pairs ----
        const float* As = Asb + st * 128 * 36;
        const float* Wf = Wfs + st * 4096;
#pragma unroll
        for (int ksp = 0; ksp < 2; ksp++) {
            unsigned a[2][2][4];     // [half][mt][reg]
#pragma unroll
            for (int h = 0; h < 2; h++) {
                int ks = 2 * ksp + h;
#pragma unroll
                for (int mt = 0; mt < 2; mt++) {
                    a[h][mt][0] = U(As[(wm + mt * 16 + g    ) * 36 + ks * 8 + t4    ]);
                    a[h][mt][1] = U(As[(wm + mt * 16 + g + 8) * 36 + ks * 8 + t4    ]);
                    a[h][mt][2] = U(As[(wm + mt * 16 + g    ) * 36 + ks * 8 + t4 + 4]);
                    a[h][mt][3] = U(As[(wm + mt * 16 + g + 8) * 36 + ks * 8 + t4 + 4]);
                }
            }
#pragma unroll
            for (int nt = 0; nt < 8; nt++) {
                int tileB = (ntb + nt) * 2 + ksp;
                float4 Bv = *(const float4*)&Wf[tileB * 128 + lane * 4];
                mma_tf32(acc[0][nt], a[0][0][0], a[0][0][1], a[0][0][2], a[0][0][3], U(Bv.x), U(Bv.y));
                mma_tf32(acc[1][nt], a[0][1][0], a[0][1][1], a[0][1][2], a[0][1][3], U(Bv.x), U(Bv.y));
                mma_tf32(acc[0][nt], a[1][0][0], a[1][0][1], a[1][0][2], a[1][0][3], U(Bv.z), U(Bv.w));
                mma_tf32(acc[1][nt], a[1][1][0], a[1][1][1], a[1][1][2], a[1][1][3], U(Bv.z), U(Bv.w));
            }
        }
    }

    // scatter epilogue into fragment-tile layout
#pragma unroll
    for (int mt = 0; mt < 2; mt++) {
#pragma unroll
        for (int nt = 0; nt < 8; nt++) {
            int row = m0 + wm + mt * 16 + g;
            int col = ntb * 8 + nt * 8 + 2 * t4;
            outp[frag_idx(w3, row,     col    )] = f2tf(acc[mt][nt][0] * oscale);
            outp[frag_idx(w3, row,     col + 1)] = f2tf(acc[mt][nt][1] * oscale);
            outp[frag_idx(w3, row + 8, col    )] = f2tf(acc[mt][nt][2] * oscale);
            outp[frag_idx(w3, row + 8, col + 1)] = f2tf(acc[mt][nt][3] * oscale);
        }
    }
}

// ---------------------------------------------------------------------------
// Kernel 2: causal flash attention (unchanged from R15 — measured 114 us).
// ---------------------------------------------------------------------------
#define ATTN_SMEM ((16384 + 16384 + 16384) * 4)   // 196608 B

__global__ __launch_bounds__(256, 1) void attn_kernel(float* __restrict__ out)
{
    extern __shared__ float sh[];
    float* Qf = sh;
    float* Kf = Qf + 16384;
    float* Vf = Kf + 16384;

    const int b  = blockIdx.y;
    const int qt = blockIdx.x;
    const int q0 = qt * 128;
    const int nkt = 2 * qt + 2;

    const int tid  = threadIdx.x;
    const int lane = tid & 31;
    const int w    = tid >> 5;
    const int g    = lane >> 2;
    const int t4   = lane & 3;
    const int qoff = (w >> 2) * 8192 + (w & 3) * 16 * 128;
    const int row1 = q0 + 16 * w + g;
    const int row2 = row1 + 8;

    const float4* Qg4 = (const float4*)(g_Q + ((size_t)b * 32 + 2 * qt) * 8192);
#pragma unroll
    for (int i = 0; i < 16; i++) {
        int lin = tid + i * 256;
        *(float4*)&Qf[lin * 4] = Qg4[lin];
    }

    {
        const char* Kg = (const char*)(g_K + (size_t)b * 32 * 8192);
        const char* Vg = (const char*)(g_V + (size_t)b * 32 * 8192);
        unsigned kbase = (unsigned)__cvta_generic_to_shared(Kf);
        unsigned vbase = (unsigned)__cvta_generic_to_shared(Vf);
#pragma unroll
        for (int i = 0; i < 8; i++) {
            int lin = tid + i * 256;
            cp_async16(kbase + lin * 16, Kg + lin * 16);
            cp_async16(vbase + lin * 16, Vg + lin * 16);
        }
        CP_COMMIT();
    }

    float m1 = -1e30f, m2 = -1e30f, l1 = 0.f, l2 = 0.f;
    float o[16][4];
#pragma unroll
    for (int nt = 0; nt < 16; nt++)
#pragma unroll
        for (int i = 0; i < 4; i++) o[nt][i] = 0.f;

    for (int kt = 0; kt < nkt; kt++) {
        CP_WAIT0();
        __syncthreads();

        if (kt + 1 < nkt) {
            int st = (kt + 1) & 1;
            const char* Kg = (const char*)(g_K + ((size_t)b * 32 + kt + 1) * 8192);
            const char* Vg = (const char*)(g_V + ((size_t)b * 32 + kt + 1) * 8192);
            unsigned kbase = (unsigned)__cvta_generic_to_shared(Kf + st * 8192);
            unsigned vbase = (unsigned)__cvta_generic_to_shared(Vf + st * 8192);
#pragma unroll
            for (int i = 0; i < 8; i++) {
                int lin = tid + i * 256;
                cp_async16(kbase + lin * 16, Kg + lin * 16);
                cp_async16(vbase + lin * 16, Vg + lin * 16);
            }
            CP_COMMIT();
        }

        if (kt == 2 * qt + 1 && w < 4) continue;

        float* Ks = Kf + (kt & 1) * 8192;
        float* Vs = Vf + (kt & 1) * 8192;

        float s[8][4];
#pragma unroll
        for (int nt = 0; nt < 8; nt++)
#pragma unroll
            for (int i = 0; i < 4; i++) s[nt][i] = 0.f;

#pragma unroll
        for (int ksp = 0; ksp < 8; ksp++) {
            float4 A0 = *(float4*)&Qf[qoff + (2 * ksp    ) * 128 + lane * 4];
            float4 A1 = *(float4*)&Qf[qoff + (2 * ksp + 1) * 128 + lane * 4];
#pragma unroll
            for (int nt = 0; nt < 8; nt++) {
                float4 Bv = *(float4*)&Ks[(nt * 8 + ksp) * 128 + lane * 4];
                mma_tf32(s[nt], U(A0.x), U(A0.y), U(A0.z), U(A0.w), U(Bv.x), U(Bv.y));
                mma_tf32(s[nt], U(A1.x), U(A1.y), U(A1.z), U(A1.w), U(Bv.z), U(Bv.w));
            }
        }

        if (kt >= 2 * qt) {
            int cb = kt * 64;
#pragma unroll
            for (int nt = 0; nt < 8; nt++) {
                int c0 = cb + nt * 8 + 2 * t4;
                if (c0     > row1) s[nt][0] = -1e30f;
                if (c0 + 1 > row1) s[nt][1] = -1e30f;
                if (c0     > row2) s[nt][2] = -1e30f;
                if (c0 + 1 > row2) s[nt][3] = -1e30f;
            }
        }

        float mx1 = -1e30f, mx2 = -1e30f;
#pragma unroll
        for (int nt = 0; nt < 8; nt++) {
            mx1 = fmaxf(mx1, fmaxf(s[nt][0], s[nt][1]));
            mx2 = fmaxf(mx2, fmaxf(s[nt][2], s[nt][3]));
        }
        mx1 = fmaxf(mx1, __shfl_xor_sync(0xffffffffu, mx1, 1));
        mx1 = fmaxf(mx1, __shfl_xor_sync(0xffffffffu, mx1, 2));
        mx2 = fmaxf(mx2, __shfl_xor_sync(0xffffffffu, mx2, 1));
        mx2 = fmaxf(mx2, __shfl_xor_sync(0xffffffffu, mx2, 2));

        float mn1 = fmaxf(m1, mx1), mn2 = fmaxf(m2, mx2);
        float al1 = __expf(m1 - mn1), al2 = __expf(m2 - mn2);
        m1 = mn1; m2 = mn2;

        float sum1 = 0.f, sum2 = 0.f;
#pragma unroll
        for (int nt = 0; nt < 8; nt++) {
            float p0 = __expf(s[nt][0] - mn1);
            float p1 = __expf(s[nt][1] - mn1);
            float p2 = __expf(s[nt][2] - mn2);
            float p3 = __expf(s[nt][3] - mn2);
            sum1 += p0 + p1; sum2 += p2 + p3;
            s[nt][0] = f2tf(p0); s[nt][1] = f2tf(p1);
            s[nt][2] = f2tf(p2); s[nt][3] = f2tf(p3);
        }
        sum1 += __shfl_xor_sync(0xffffffffu, sum1, 1);
        sum1 += __shfl_xor_sync(0xffffffffu, sum1, 2);
        sum2 += __shfl_xor_sync(0xffffffffu, sum2, 1);
        sum2 += __shfl_xor_sync(0xffffffffu, sum2, 2);
        l1 = l1 * al1 + sum1;
        l2 = l2 * al2 + sum2;

#pragma unroll
        for (int nt = 0; nt < 16; nt++) {
            o[nt][0] *= al1; o[nt][1] *= al1;
            o[nt][2] *= al2; o[nt][3] *= al2;
        }

#pragma unroll
        for (int ksp = 0; ksp < 4; ksp++) {
            unsigned a[2][4];
#pragma unroll
            for (int h = 0; h < 2; h++) {
                int j = 2 * ksp + h;
                float p0 = s[j][0], p1 = s[j][1], p2 = s[j][2], p3 = s[j][3];
                int srcA = (lane & ~3) | (t4 >> 1);
                int srcB = srcA + 2;
                float u0 = __shfl_sync(0xffffffffu, p0, srcA);
                float v0 = __shfl_sync(0xffffffffu, p1, srcA);
                float u1 = __shfl_sync(0xffffffffu, p2, srcA);
                float v1 = __shfl_sync(0xffffffffu, p3, srcA);
                float u2 = __shfl_sync(0xffffffffu, p0, srcB);
                float v2 = __shfl_sync(0xffffffffu, p1, srcB);
                float u3 = __shfl_sync(0xffffffffu, p2, srcB);
                float v3 = __shfl_sync(0xffffffffu, p3, srcB);
                bool odd = (t4 & 1);
                a[h][0] = U(odd ? v0 : u0);
                a[h][1] = U(odd ? v1 : u1);
                a[h][2] = U(odd ? v2 : u2);
                a[h][3] = U(odd ? v3 : u3);
            }
#pragma unroll
            for (int nt = 0; nt < 16; nt++) {
                float4 Bv = *(float4*)&Vs[(nt * 4 + ksp) * 128 + lane * 4];
                mma_tf32(o[nt], a[0][0], a[0][1], a[0][2], a[0][3], U(Bv.x), U(Bv.y));
                mma_tf32(o[nt], a[1][0], a[1][1], a[1][2], a[1][3], U(Bv.z), U(Bv.w));
            }
        }
    }

    {
        float inv1 = 1.f / l1, inv2 = 1.f / l2;
        size_t base1 = ((size_t)b * TT + row1) * HH;
        size_t base2 = ((size_t)b * TT + row2) * HH;
#pragma unroll
        for (int nt = 0; nt < 16; nt++) {
            int col = nt * 8 + 2 * t4;
            *(float2*)&out[base1 + col] = make_float2(o[nt][0] * inv1, o[nt][1] * inv1);
            *(float2*)&out[base2 + col] = make_float2(o[nt][2] * inv2, o[nt][3] * inv2);
        }
    }
}

// ---------------------------------------------------------------------------
extern "C" void kernel_launch(void* const* d_in, const int* in_sizes, int n_in,
                              void* d_out, int out_size)
{
    const float* x  = (const float*)d_in[0];
    const float* Wq = (const float*)d_in[1];
    const float* Wk = (const float*)d_in[2];
    const float* Wv = (const float*)d_in[3];
    float* out = (float*)d_out;

    wperm_kernel<<<dim3(32, 3), 256>>>(Wq, Wk, Wv);

    cudaFuncSetAttribute(qkv_kernel,
                         cudaFuncAttributeMaxDynamicSharedMemorySize, QKV_SMEM);
    qkv_kernel<<<dim3(MM / 128, 3), 256, QKV_SMEM>>>(x, Wq, Wk, Wv);

    cudaFuncSetAttribute(attn_kernel,
                         cudaFuncAttributeMaxDynamicSharedMemorySize, ATTN_SMEM);
    attn_kernel<<<dim3(16, BB), 256, ATTN_SMEM>>>(out);
}

// round 17
// speedup vs baseline: 1.4514x; 1.4514x over previous
#include <cuda_runtime.h>

#define BB 8
#define TT 2048
#define EE 1024
#define HH 128
#define MM (BB*TT)
#define SCALE 0.08838834764831845f   // 1/sqrt(128)

// Q/K/V in FRAGMENT-TILE layout: per 64-row block, 64 tiles x 128 floats.
__device__ float g_Q[MM*HH];
__device__ float g_K[MM*HH];
__device__ float g_V[MM*HH];
// W in B-fragment-tile layout (tf32-rounded): per 32-k block, 32 tiles x 128.
__device__ float g_Wf[3][EE*HH];

__device__ __forceinline__ float f2tf(float f) {
    unsigned r;
    asm("cvt.rna.tf32.f32 %0, %1;" : "=r"(r) : "f"(f));
    return __uint_as_float(r);
}

__device__ __forceinline__ void mma_tf32(float* c,
    unsigned a0, unsigned a1, unsigned a2, unsigned a3,
    unsigned b0, unsigned b1)
{
    asm volatile(
        "mma.sync.aligned.m16n8k8.row.col.f32.tf32.tf32.f32 "
        "{%0,%1,%2,%3},{%4,%5,%6,%7},{%8,%9},{%0,%1,%2,%3};"
        : "+f"(c[0]), "+f"(c[1]), "+f"(c[2]), "+f"(c[3])
        : "r"(a0), "r"(a1), "r"(a2), "r"(a3), "r"(b0), "r"(b1));
}
#define U(x) __float_as_uint(x)

__device__ __forceinline__ void cp_async16(unsigned saddr, const void* gaddr) {
    asm volatile("cp.async.cg.shared.global [%0], [%1], 16;"
                 :: "r"(saddr), "l"(gaddr));
}
#define CP_COMMIT() asm volatile("cp.async.commit_group;")
#define CP_WAIT0()  asm volatile("cp.async.wait_group 0;")

// Scatter index into Q/K/V fragment-tile layout (per 64-row block of 8192).
__device__ __forceinline__ size_t frag_idx(int w3, int m, int c) {
    int blk = m >> 6, R = m & 63;
    int tile, lane, reg;
    if (w3 == 0) {
        tile = (R >> 4) * 16 + (c >> 3);
        lane = ((R & 7) << 2) | (c & 3);
        reg  = ((R >> 3) & 1) | (((c >> 2) & 1) << 1);
    } else if (w3 == 1) {
        tile = (R >> 3) * 8 + (c >> 4);
        lane = ((R & 7) << 2) | (c & 3);
        reg  = (c >> 2) & 3;
    } else {
        tile = (c >> 3) * 4 + (R >> 4);
        lane = ((c & 7) << 2) | (R & 3);
        reg  = (R >> 2) & 3;
    }
    return (size_t)blk * 8192 + tile * 128 + lane * 4 + reg;
}

// ---------------------------------------------------------------------------
// Kernel 0: permute W[E,H] -> B-frag tiles (per 32-k block: 32 tiles x 128).
// ---------------------------------------------------------------------------
__global__ __launch_bounds__(256) void wperm_kernel(
    const float* __restrict__ Wq,
    const float* __restrict__ Wk,
    const float* __restrict__ Wv)
{
    const int blk = blockIdx.x;           // 32-k block, 0..31
    const int w3  = blockIdx.y;
    const float* Wp = (w3 == 0) ? Wq : ((w3 == 1) ? Wk : Wv);
    float* outp = g_Wf[w3] + blk * 4096;

    for (int e = 0; e < 16; e++) {
        int idx = threadIdx.x + e * 256;  // 0..4095
        int kk = idx >> 7;                // local k, 0..31
        int n  = idx & 127;
        float v = Wp[(size_t)(blk * 32 + kk) * HH + n];
        int kc = kk & 15;
        int tile = (n >> 3) * 2 + (kk >> 4);
        int lane = ((n & 7) << 2) | (kc & 3);
        int reg  = kc >> 2;
        outp[tile * 128 + lane * 4 + reg] = f2tf(v);
    }
}

// ---------------------------------------------------------------------------
// Kernel 1: QKV projection. cp.async 2-stage W (pre-permuted frag tiles),
// double-buffered As, ONE barrier per 32-k iteration. Fragment scatter epi.
// NO min-blocks clause: let registers float (R16's (256,2) cap caused spills).
// ---------------------------------------------------------------------------
#define QKV_SMEM ((2*128*36 + 2*4096) * 4)

__global__ __launch_bounds__(256) void qkv_kernel(
    const float* __restrict__ x,
    const float* __restrict__ Wq,
    const float* __restrict__ Wk,
    const float* __restrict__ Wv)
{
    extern __shared__ float sh2[];
    float* Asb = sh2;                 // 2 stages x [128][36]
    float* Wfs = sh2 + 2 * 128 * 36;  // 2 stages x 4096

    const int mb = blockIdx.x;
    const int w3 = blockIdx.y;
    float* outp = (w3 == 0) ? g_Q : ((w3 == 1) ? g_K : g_V);
    const float oscale = (w3 == 0) ? SCALE : 1.0f;
    const float* Wfg = g_Wf[w3];

    const int tid  = threadIdx.x;
    const int lane = tid & 31;
    const int w    = tid >> 5;
    const int g    = lane >> 2;
    const int t4   = lane & 3;
    const int wm   = (w >> 1) * 32;
    const int ntb  = (w & 1) * 8;     // base n-tile for this warp
    const int m0   = mb * 128;

    float acc[2][8][4];
#pragma unroll
    for (int mt = 0; mt < 2; mt++)
#pragma unroll
        for (int nt = 0; nt < 8; nt++)
#pragma unroll
            for (int i = 0; i < 4; i++) acc[mt][nt][i] = 0.f;

    // ---- prologue ----
    float4 xa[4];
#pragma unroll
    for (int i = 0; i < 4; i++) {           // prefetch x block 0
        int lin = tid + i * 256;
        int r = lin >> 3, c = (lin & 7) * 4;
        xa[i] = *(const float4*)&x[(size_t)(m0 + r) * EE + c];
    }
#pragma unroll
    for (int i = 0; i < 4; i++) {           // fill As stage 0
        int lin = tid + i * 256;
        int r = lin >> 3, c = (lin & 7) * 4;
        float* As0 = Asb + r * 36 + c;
        As0[0] = f2tf(xa[i].x); As0[1] = f2tf(xa[i].y);
        As0[2] = f2tf(xa[i].z); As0[3] = f2tf(xa[i].w);
    }
#pragma unroll
    for (int i = 0; i < 4; i++) {           // prefetch x block 1
        int lin = tid + i * 256;
        int r = lin >> 3, c = (lin & 7) * 4;
        xa[i] = *(const float4*)&x[(size_t)(m0 + r) * EE + 32 + c];
    }
    {                                        // cp.async W block 0 -> stage 0
        unsigned wb = (unsigned)__cvta_generic_to_shared(Wfs);
#pragma unroll
        for (int i = 0; i < 4; i++) {
            int lin = tid + i * 256;
            cp_async16(wb + lin * 16, (const char*)Wfg + lin * 16);
        }
        CP_COMMIT();
    }

    for (int it = 0; it < 32; it++) {
        const int st = it & 1;
        CP_WAIT0();
        __syncthreads();      // W[it] + As[it] visible; prev compute done

        if (it + 1 < 32) {
            // cp.async W block it+1 into other stage
            unsigned wb = (unsigned)__cvta_generic_to_shared(Wfs + (st ^ 1) * 4096);
            const char* wg = (const char*)(Wfg + (size_t)(it + 1) * 4096);
#pragma unroll
            for (int i = 0; i < 4; i++) {
                int lin = tid + i * 256;
                cp_async16(wb + lin * 16, wg + lin * 16);
            }
            CP_COMMIT();
            // fill As other stage from xa (block it+1)
            float* Asn = Asb + (st ^ 1) * 128 * 36;
#pragma unroll
            for (int i = 0; i < 4; i++) {
                int lin = tid + i * 256;
                int r = lin >> 3, c = (lin & 7) * 4;
                float* p = Asn + r * 36 + c;
                p[0] = f2tf(xa[i].x); p[1] = f2tf(xa[i].y);
                p[2] = f2tf(xa[i].z); p[3] = f2tf(xa[i].w);
            }
            // prefetch x block it+2
            if (it + 2 < 32) {
                int kn = (it + 2) * 32;
#pragma unroll
                for (int i = 0; i < 4; i++) {
                    int lin = tid + i * 256;
                    int r = lin >> 3, c = (lin & 7) * 4;
                    xa[i] = *(const float4*)&x[(size_t)(m0 + r) * EE + kn + c];
                }
            }
        }

        // ---- compute: 4 k-steps as 2 ksp pairs ----
        const float* As = Asb + st * 128 * 36;
        const float* Wf = Wfs + st * 4096;
#pragma unroll
        for (int ksp = 0; ksp < 2; ksp++) {
            unsigned a[2][2][4];     // [half][mt][reg]
#pragma unroll
            for (int h = 0; h < 2; h++) {
                int ks = 2 * ksp + h;
#pragma unroll
                for (int mt = 0; mt < 2; mt++) {
                    a[h][mt][0] = U(As[(wm + mt * 16 + g    ) * 36 + ks * 8 + t4    ]);
                    a[h][mt][1] = U(As[(wm + mt * 16 + g + 8) * 36 + ks * 8 + t4    ]);
                    a[h][mt][2] = U(As[(wm + mt * 16 + g    ) * 36 + ks * 8 + t4 + 4]);
                    a[h][mt][3] = U(As[(wm + mt * 16 + g + 8) * 36 + ks * 8 + t4 + 4]);
                }
            }
#pragma unroll
            for (int nt = 0; nt < 8; nt++) {
                int tileB = (ntb + nt) * 2 + ksp;
                float4 Bv = *(const float4*)&Wf[tileB * 128 + lane * 4];
                mma_tf32(acc[0][nt], a[0][0][0], a[0][0][1], a[0][0][2], a[0][0][3], U(Bv.x), U(Bv.y));
                mma_tf32(acc[1][nt], a[0][1][0], a[0][1][1], a[0][1][2], a[0][1][3], U(Bv.x), U(Bv.y));
                mma_tf32(acc[0][nt], a[1][0][0], a[1][0][1], a[1][0][2], a[1][0][3], U(Bv.z), U(Bv.w));
                mma_tf32(acc[1][nt], a[1][1][0], a[1][1][1], a[1][1][2], a[1][1][3], U(Bv.z), U(Bv.w));
            }
        }
    }

    // scatter epilogue into fragment-tile layout
#pragma unroll
    for (int mt = 0; mt < 2; mt++) {
#pragma unroll
        for (int nt = 0; nt < 8; nt++) {
            int row = m0 + wm + mt * 16 + g;
            int col = ntb * 8 + nt * 8 + 2 * t4;
            outp[frag_idx(w3, row,     col    )] = f2tf(acc[mt][nt][0] * oscale);
            outp[frag_idx(w3, row,     col + 1)] = f2tf(acc[mt][nt][1] * oscale);
            outp[frag_idx(w3, row + 8, col    )] = f2tf(acc[mt][nt][2] * oscale);
            outp[frag_idx(w3, row + 8, col + 1)] = f2tf(acc[mt][nt][3] * oscale);
        }
    }
}

// ---------------------------------------------------------------------------
// Kernel 2: causal flash attention (unchanged from R15 — measured 114 us).
// ---------------------------------------------------------------------------
#define ATTN_SMEM ((16384 + 16384 + 16384) * 4)   // 196608 B

__global__ __launch_bounds__(256, 1) void attn_kernel(float* __restrict__ out)
{
    extern __shared__ float sh[];
    float* Qf = sh;
    float* Kf = Qf + 16384;
    float* Vf = Kf + 16384;

    const int b  = blockIdx.y;
    const int qt = blockIdx.x;
    const int q0 = qt * 128;
    const int nkt = 2 * qt + 2;

    const int tid  = threadIdx.x;
    const int lane = tid & 31;
    const int w    = tid >> 5;
    const int g    = lane >> 2;
    const int t4   = lane & 3;
    const int qoff = (w >> 2) * 8192 + (w & 3) * 16 * 128;
    const int row1 = q0 + 16 * w + g;
    const int row2 = row1 + 8;

    const float4* Qg4 = (const float4*)(g_Q + ((size_t)b * 32 + 2 * qt) * 8192);
#pragma unroll
    for (int i = 0; i < 16; i++) {
        int lin = tid + i * 256;
        *(float4*)&Qf[lin * 4] = Qg4[lin];
    }

    {
        const char* Kg = (const char*)(g_K + (size_t)b * 32 * 8192);
        const char* Vg = (const char*)(g_V + (size_t)b * 32 * 8192);
        unsigned kbase = (unsigned)__cvta_generic_to_shared(Kf);
        unsigned vbase = (unsigned)__cvta_generic_to_shared(Vf);
#pragma unroll
        for (int i = 0; i < 8; i++) {
            int lin = tid + i * 256;
            cp_async16(kbase + lin * 16, Kg + lin * 16);
            cp_async16(vbase + lin * 16, Vg + lin * 16);
        }
        CP_COMMIT();
    }

    float m1 = -1e30f, m2 = -1e30f, l1 = 0.f, l2 = 0.f;
    float o[16][4];
#pragma unroll
    for (int nt = 0; nt < 16; nt++)
#pragma unroll
        for (int i = 0; i < 4; i++) o[nt][i] = 0.f;

    for (int kt = 0; kt < nkt; kt++) {
        CP_WAIT0();
        __syncthreads();

        if (kt + 1 < nkt) {
            int st = (kt + 1) & 1;
            const char* Kg = (const char*)(g_K + ((size_t)b * 32 + kt + 1) * 8192);
            const char* Vg = (const char*)(g_V + ((size_t)b * 32 + kt + 1) * 8192);
            unsigned kbase = (unsigned)__cvta_generic_to_shared(Kf + st * 8192);
            unsigned vbase = (unsigned)__cvta_generic_to_shared(Vf + st * 8192);
#pragma unroll
            for (int i = 0; i < 8; i++) {
                int lin = tid + i * 256;
                cp_async16(kbase + lin * 16, Kg + lin * 16);
                cp_async16(vbase + lin * 16, Vg + lin * 16);
            }
            CP_COMMIT();
        }

        if (kt == 2 * qt + 1 && w < 4) continue;

        float* Ks = Kf + (kt & 1) * 8192;
        float* Vs = Vf + (kt & 1) * 8192;

        float s[8][4];
#pragma unroll
        for (int nt = 0; nt < 8; nt++)
#pragma unroll
            for (int i = 0; i < 4; i++) s[nt][i] = 0.f;

#pragma unroll
        for (int ksp = 0; ksp < 8; ksp++) {
            float4 A0 = *(float4*)&Qf[qoff + (2 * ksp    ) * 128 + lane * 4];
            float4 A1 = *(float4*)&Qf[qoff + (2 * ksp + 1) * 128 + lane * 4];
#pragma unroll
            for (int nt = 0; nt < 8; nt++) {
                float4 Bv = *(float4*)&Ks[(nt * 8 + ksp) * 128 + lane * 4];
                mma_tf32(s[nt], U(A0.x), U(A0.y), U(A0.z), U(A0.w), U(Bv.x), U(Bv.y));
                mma_tf32(s[nt], U(A1.x), U(A1.y), U(A1.z), U(A1.w), U(Bv.z), U(Bv.w));
            }
        }

        if (kt >= 2 * qt) {
            int cb = kt * 64;
#pragma unroll
            for (int nt = 0; nt < 8; nt++) {
                int c0 = cb + nt * 8 + 2 * t4;
                if (c0     > row1) s[nt][0] = -1e30f;
                if (c0 + 1 > row1) s[nt][1] = -1e30f;
                if (c0     > row2) s[nt][2] = -1e30f;
                if (c0 + 1 > row2) s[nt][3] = -1e30f;
            }
        }

        float mx1 = -1e30f, mx2 = -1e30f;
#pragma unroll
        for (int nt = 0; nt < 8; nt++) {
            mx1 = fmaxf(mx1, fmaxf(s[nt][0], s[nt][1]));
            mx2 = fmaxf(mx2, fmaxf(s[nt][2], s[nt][3]));
        }
        mx1 = fmaxf(mx1, __shfl_xor_sync(0xffffffffu, mx1, 1));
        mx1 = fmaxf(mx1, __shfl_xor_sync(0xffffffffu, mx1, 2));
        mx2 = fmaxf(mx2, __shfl_xor_sync(0xffffffffu, mx2, 1));
        mx2 = fmaxf(mx2, __shfl_xor_sync(0xffffffffu, mx2, 2));

        float mn1 = fmaxf(m1, mx1), mn2 = fmaxf(m2, mx2);
        float al1 = __expf(m1 - mn1), al2 = __expf(m2 - mn2);
        m1 = mn1; m2 = mn2;

        float sum1 = 0.f, sum2 = 0.f;
#pragma unroll
        for (int nt = 0; nt < 8; nt++) {
            float p0 = __expf(s[nt][0] - mn1);
            float p1 = __expf(s[nt][1] - mn1);
            float p2 = __expf(s[nt][2] - mn2);
            float p3 = __expf(s[nt][3] - mn2);
            sum1 += p0 + p1; sum2 += p2 + p3;
            s[nt][0] = f2tf(p0); s[nt][1] = f2tf(p1);
            s[nt][2] = f2tf(p2); s[nt][3] = f2tf(p3);
        }
        sum1 += __shfl_xor_sync(0xffffffffu, sum1, 1);
        sum1 += __shfl_xor_sync(0xffffffffu, sum1, 2);
        sum2 += __shfl_xor_sync(0xffffffffu, sum2, 1);
        sum2 += __shfl_xor_sync(0xffffffffu, sum2, 2);
        l1 = l1 * al1 + sum1;
        l2 = l2 * al2 + sum2;

#pragma unroll
        for (int nt = 0; nt < 16; nt++) {
            o[nt][0] *= al1; o[nt][1] *= al1;
            o[nt][2] *= al2; o[nt][3] *= al2;
        }

#pragma unroll
        for (int ksp = 0; ksp < 4; ksp++) {
            unsigned a[2][4];
#pragma unroll
            for (int h = 0; h < 2; h++) {
                int j = 2 * ksp + h;
                float p0 = s[j][0], p1 = s[j][1], p2 = s[j][2], p3 = s[j][3];
                int srcA = (lane & ~3) | (t4 >> 1);
                int srcB = srcA + 2;
                float u0 = __shfl_sync(0xffffffffu, p0, srcA);
                float v0 = __shfl_sync(0xffffffffu, p1, srcA);
                float u1 = __shfl_sync(0xffffffffu, p2, srcA);
                float v1 = __shfl_sync(0xffffffffu, p3, srcA);
                float u2 = __shfl_sync(0xffffffffu, p0, srcB);
                float v2 = __shfl_sync(0xffffffffu, p1, srcB);
                float u3 = __shfl_sync(0xffffffffu, p2, srcB);
                float v3 = __shfl_sync(0xffffffffu, p3, srcB);
                bool odd = (t4 & 1);
                a[h][0] = U(odd ? v0 : u0);
                a[h][1] = U(odd ? v1 : u1);
                a[h][2] = U(odd ? v2 : u2);
                a[h][3] = U(odd ? v3 : u3);
            }
#pragma unroll
            for (int nt = 0; nt < 16; nt++) {
                float4 Bv = *(float4*)&Vs[(nt * 4 + ksp) * 128 + lane * 4];
                mma_tf32(o[nt], a[0][0], a[0][1], a[0][2], a[0][3], U(Bv.x), U(Bv.y));
                mma_tf32(o[nt], a[1][0], a[1][1], a[1][2], a[1][3], U(Bv.z), U(Bv.w));
            }
        }
    }

    {
        float inv1 = 1.f / l1, inv2 = 1.f / l2;
        size_t base1 = ((size_t)b * TT + row1) * HH;
        size_t base2 = ((size_t)b * TT + row2) * HH;
#pragma unroll
        for (int nt = 0; nt < 16; nt++) {
            int col = nt * 8 + 2 * t4;
            *(float2*)&out[base1 + col] = make_float2(o[nt][0] * inv1, o[nt][1] * inv1);
            *(float2*)&out[base2 + col] = make_float2(o[nt][2] * inv2, o[nt][3] * inv2);
        }
    }
}

// ---------------------------------------------------------------------------
extern "C" void kernel_launch(void* const* d_in, const int* in_sizes, int n_in,
                              void* d_out, int out_size)
{
    const float* x  = (const float*)d_in[0];
    const float* Wq = (const float*)d_in[1];
    const float* Wk = (const float*)d_in[2];
    const float* Wv = (const float*)d_in[3];
    float* out = (float*)d_out;

    wperm_kernel<<<dim3(32, 3), 256>>>(Wq, Wk, Wv);

    cudaFuncSetAttribute(qkv_kernel,
                         cudaFuncAttributeMaxDynamicSharedMemorySize, QKV_SMEM);
    qkv_kernel<<<dim3(MM / 128, 3), 256, QKV_SMEM>>>(x, Wq, Wk, Wv);

    cudaFuncSetAttribute(attn_kernel,
                         cudaFuncAttributeMaxDynamicSharedMemorySize, ATTN_SMEM);
    attn_kernel<<<dim3(16, BB), 256, ATTN_SMEM>>>(out);
}